// round 1
// baseline (speedup 1.0000x reference)
#include <cuda_runtime.h>

// Problem constants
#define Bsz 8
#define Nn  1024
#define Pp  16
#define Dd  512
#define Ee  8192   // P*D
#define Mm  8192   // B*N

// Scratch (device globals: allocation-free kernel_launch)
__device__ float g_H[(size_t)Mm * Dd];       // 16 MB   relu(xp@W1+b1)
__device__ float g_E[(size_t)Mm * Ee];       // 256 MB  exp(relu(H@W2+b2))
__device__ float g_Zpart[64 * Ee];           // 2 MB    per-row-tile column sums
__device__ float g_Zinv[Bsz * Ee];           // 256 KB  1/softmax denominator

// ---------------------------------------------------------------------------
// K1: H[row][d] = relu(sum_p xp[row][p] * W1[p][d] + b1[d])
// ---------------------------------------------------------------------------
__global__ void k_hidden(const float* __restrict__ x,
                         const float* __restrict__ W1,
                         const float* __restrict__ b1) {
    int row = blockIdx.x;           // 0..8191
    __shared__ float xs[Pp];
    int tid = threadIdx.x;          // 0..511 (= d)
    if (tid < Pp) xs[tid] = x[row * Pp + tid];
    __syncthreads();
    float acc = b1[tid];
#pragma unroll
    for (int p = 0; p < Pp; p++) acc = fmaf(xs[p], W1[p * Dd + tid], acc);
    g_H[(size_t)row * Dd + tid] = fmaxf(acc, 0.0f);
}

// ---------------------------------------------------------------------------
// K2: tiled SGEMM  E = exp(relu(H @ W2 + b2)),  plus per-tile column sums.
// BM=BN=128, BK=16, 256 threads, 8x8 per thread (4+4 split for conflict-free LDS.128)
// ---------------------------------------------------------------------------
#define BM 128
#define BN 128
#define BK 16
#define SPAD 4

__global__ __launch_bounds__(256, 2)
void k_gemm(const float* __restrict__ W2, const float* __restrict__ b2) {
    __shared__ float As[BK][BM + SPAD];
    __shared__ float Bs[BK][BN + SPAD];
    __shared__ float red[16][BN];

    int ct = blockIdx.x;            // 0..63 col tile
    int rt = blockIdx.y;            // 0..63 row tile (each tile within one batch b)
    int row0 = rt * BM, col0 = ct * BN;
    int tid = threadIdx.x;
    int tx = tid & 15, ty = tid >> 4;

    float acc[8][8];
#pragma unroll
    for (int i = 0; i < 8; i++)
#pragma unroll
        for (int j = 0; j < 8; j++) acc[i][j] = 0.f;

    for (int k0 = 0; k0 < Dd; k0 += BK) {
        // Load A tile (128 rows x 16 k), store transposed As[k][r]
#pragma unroll
        for (int l = 0; l < 2; l++) {
            int f = tid * 2 + l;                 // 0..511 float4 id
            int r = f >> 2, q = (f & 3) * 4;
            float4 v = *reinterpret_cast<const float4*>(
                &g_H[(size_t)(row0 + r) * Dd + k0 + q]);
            As[q + 0][r] = v.x; As[q + 1][r] = v.y;
            As[q + 2][r] = v.z; As[q + 3][r] = v.w;
        }
        // Load B tile (16 k x 128 cols)
#pragma unroll
        for (int l = 0; l < 2; l++) {
            int f = tid * 2 + l;
            int kk = f >> 5, c = (f & 31) * 4;
            float4 v = *reinterpret_cast<const float4*>(
                &W2[(size_t)(k0 + kk) * Ee + col0 + c]);
            *reinterpret_cast<float4*>(&Bs[kk][c]) = v;
        }
        __syncthreads();

#pragma unroll
        for (int kk = 0; kk < BK; kk++) {
            float a[8], b[8];
            *(float4*)&a[0] = *(const float4*)&As[kk][ty * 4];
            *(float4*)&a[4] = *(const float4*)&As[kk][64 + ty * 4];
            *(float4*)&b[0] = *(const float4*)&Bs[kk][tx * 4];
            *(float4*)&b[4] = *(const float4*)&Bs[kk][64 + tx * 4];
#pragma unroll
            for (int i = 0; i < 8; i++)
#pragma unroll
                for (int j = 0; j < 8; j++)
                    acc[i][j] = fmaf(a[i], b[j], acc[i][j]);
        }
        __syncthreads();
    }

    // Epilogue: bias + relu + exp, write E, accumulate column sums
    float bias[8];
#pragma unroll
    for (int j = 0; j < 8; j++) {
        int c = (j < 4) ? tx * 4 + j : 64 + tx * 4 + (j - 4);
        bias[j] = b2[col0 + c];
    }
    float csum[8] = {0, 0, 0, 0, 0, 0, 0, 0};
#pragma unroll
    for (int i = 0; i < 8; i++) {
        int r = (i < 4) ? ty * 4 + i : 64 + ty * 4 + (i - 4);
        float ov[8];
#pragma unroll
        for (int j = 0; j < 8; j++) {
            float v = __expf(fmaxf(acc[i][j] + bias[j], 0.0f));
            ov[j] = v;
            csum[j] += v;
        }
        size_t base = (size_t)(row0 + r) * Ee + col0;
        *(float4*)&g_E[base + tx * 4]      = make_float4(ov[0], ov[1], ov[2], ov[3]);
        *(float4*)&g_E[base + 64 + tx * 4] = make_float4(ov[4], ov[5], ov[6], ov[7]);
    }

    // Deterministic in-block column reduction (no atomics)
#pragma unroll
    for (int j = 0; j < 8; j++) {
        int c = (j < 4) ? tx * 4 + j : 64 + tx * 4 + (j - 4);
        red[ty][c] = csum[j];
    }
    __syncthreads();
    if (tid < BN) {
        float s = 0.f;
#pragma unroll
        for (int t = 0; t < 16; t++) s += red[t][tid];
        g_Zpart[(size_t)rt * Ee + col0 + tid] = s;
    }
}

// ---------------------------------------------------------------------------
// K2b: Zinv[b][e] = 1 / sum over the 8 row tiles of batch b
// ---------------------------------------------------------------------------
__global__ void k_zreduce() {
    int idx = blockIdx.x * blockDim.x + threadIdx.x;  // 0..65535
    int b = idx >> 13;
    int e = idx & (Ee - 1);
    float s = 0.f;
#pragma unroll
    for (int i = 0; i < 8; i++) s += g_Zpart[(size_t)(b * 8 + i) * Ee + e];
    g_Zinv[idx] = 1.0f / s;
}

// ---------------------------------------------------------------------------
// K3: normalize, multiply by xp, transpose (d,p)->(p,d), avgpool3 over d.
// out[b, n*16+p, d] = xp[b,n,p]/3 * (S[d-1,p] + S[d,p] + S[d+1,p])
// smem t stored [p][d] with stride 514 -> conflict-free store & read.
// ---------------------------------------------------------------------------
__global__ void k_final(const float* __restrict__ x, float* __restrict__ out) {
    int row = blockIdx.x;           // b*1024 + n
    int b = row >> 10;
    __shared__ float t[Pp * 514];
    __shared__ float xs[Pp];
    int tid = threadIdx.x;          // 0..511
    if (tid < Pp) xs[tid] = x[row * Pp + tid] * (1.0f / 3.0f);
    const float* Erow = g_E + (size_t)row * Ee;
    const float* Zb = g_Zinv + b * Ee;
#pragma unroll
    for (int e = tid; e < Ee; e += 512) {
        float v = Erow[e] * Zb[e];
        int d = e >> 4, p = e & 15;
        t[p * 514 + d] = v;
    }
    __syncthreads();
    int d = tid;
    size_t obase = ((size_t)row * Pp) * Dd + d;
#pragma unroll
    for (int p = 0; p < Pp; p++) {
        const float* tp = t + p * 514;
        float c = tp[d];
        float l = (d > 0)   ? tp[d - 1] : 0.f;
        float r = (d < 511) ? tp[d + 1] : 0.f;
        out[obase + (size_t)p * Dd] = xs[p] * (l + c + r);
    }
}

// ---------------------------------------------------------------------------
extern "C" void kernel_launch(void* const* d_in, const int* in_sizes, int n_in,
                              void* d_out, int out_size) {
    const float* x  = (const float*)d_in[0];
    const float* W1 = (const float*)d_in[1];
    const float* b1 = (const float*)d_in[2];
    const float* W2 = (const float*)d_in[3];
    const float* b2 = (const float*)d_in[4];
    float* out = (float*)d_out;

    k_hidden<<<Mm, Dd>>>(x, W1, b1);
    dim3 g2(Ee / BN, Mm / BM);      // (64, 64)
    k_gemm<<<g2, 256>>>(W2, b2);
    k_zreduce<<<(Bsz * Ee) / 256, 256>>>();
    k_final<<<Mm, 512>>>(x, out);
}

// round 3
// speedup vs baseline: 2.2418x; 2.2418x over previous
#include <cuda_runtime.h>
#include <cuda_bf16.h>
#include <cstdint>

#define Bsz 8
#define Pp  16
#define Dd  512
#define Ee  8192
#define Mm  8192

// Scratch (device globals)
__device__ __nv_bfloat16 g_Hh[(size_t)Mm * Dd];   // hi(bf16) of H, row-major [M][512]
__device__ __nv_bfloat16 g_Hl[(size_t)Mm * Dd];   // lo
__device__ __nv_bfloat16 g_W2h[(size_t)Ee * Dd];  // hi of W2^T, [E][512] (k contiguous)
__device__ __nv_bfloat16 g_W2l[(size_t)Ee * Dd];  // lo
__device__ float g_E[(size_t)Mm * Ee];            // 256 MB exp(relu(logits))
__device__ float g_Zpart[64 * Ee];
__device__ float g_Zinv[Bsz * Ee];

// ======================= PTX helpers (base compute_103 safe) =======================
__device__ __forceinline__ uint32_t smem_u32(const void* p) {
    uint32_t a;
    asm("{ .reg .u64 t; cvta.to.shared.u64 t, %1; cvt.u32.u64 %0, t; }" : "=r"(a) : "l"(p));
    return a;
}
#define CP16(dst, src) \
    asm volatile("cp.async.cg.shared.global [%0], [%1], 16;" :: "r"(dst), "l"(src) : "memory")
#define CP_COMMIT() asm volatile("cp.async.commit_group;" ::: "memory")
#define CP_WAIT1()  asm volatile("cp.async.wait_group 1;" ::: "memory")
#define CP_WAIT0()  asm volatile("cp.async.wait_group 0;" ::: "memory")

__device__ __forceinline__ void ldsm4(uint32_t* r, uint32_t addr) {
    asm volatile("ldmatrix.sync.aligned.m8n8.x4.shared.b16 {%0,%1,%2,%3}, [%4];"
                 : "=r"(r[0]), "=r"(r[1]), "=r"(r[2]), "=r"(r[3]) : "r"(addr));
}
__device__ __forceinline__ void mma16816(float* c, const uint32_t* a, const uint32_t* b) {
    asm volatile("mma.sync.aligned.m16n8k16.row.col.f32.bf16.bf16.f32 "
                 "{%0,%1,%2,%3}, {%4,%5,%6,%7}, {%8,%9}, {%0,%1,%2,%3};"
                 : "+f"(c[0]), "+f"(c[1]), "+f"(c[2]), "+f"(c[3])
                 : "r"(a[0]), "r"(a[1]), "r"(a[2]), "r"(a[3]), "r"(b[0]), "r"(b[1]));
}

// ======================= K1: hidden layer + bf16 split =======================
__global__ void k_hidden(const float* __restrict__ x,
                         const float* __restrict__ W1,
                         const float* __restrict__ b1) {
    int row = blockIdx.x;
    __shared__ float xs[Pp];
    int tid = threadIdx.x;                  // = d (512 threads)
    if (tid < Pp) xs[tid] = x[row * Pp + tid];
    __syncthreads();
    float acc = b1[tid];
#pragma unroll
    for (int p = 0; p < Pp; p++) acc = fmaf(xs[p], W1[p * Dd + tid], acc);
    float h = fmaxf(acc, 0.0f);
    __nv_bfloat16 hh = __float2bfloat16(h);
    float lo = h - __bfloat162float(hh);
    size_t o = (size_t)row * Dd + tid;
    g_Hh[o] = hh;
    g_Hl[o] = __float2bfloat16(lo);
}

// ======================= K1b: W2 transpose + bf16 split =======================
__global__ void k_w2conv(const float* __restrict__ W2) {
    __shared__ float ts[64][65];
    int e0 = blockIdx.x * 64, k0 = blockIdx.y * 64;
    int tid = threadIdx.x;
#pragma unroll
    for (int idx = tid; idx < 4096; idx += 256) {
        int i = idx >> 6, j = idx & 63;     // i=k, j=e
        ts[i][j] = W2[(size_t)(k0 + i) * Ee + e0 + j];
    }
    __syncthreads();
#pragma unroll
    for (int idx = tid; idx < 4096; idx += 256) {
        int j = idx >> 6, i = idx & 63;     // j=e, i=k
        float v = ts[i][j];
        __nv_bfloat16 hh = __float2bfloat16(v);
        float lo = v - __bfloat162float(hh);
        size_t o = (size_t)(e0 + j) * Dd + k0 + i;
        g_W2h[o] = hh;
        g_W2l[o] = __float2bfloat16(lo);
    }
}

// ======================= K2: mma.sync bf16x3 GEMM + fused epilogue =======================
// CTA 128x128, BK=32, 16 stages double-buffered via cp.async.
// smem tile: 128 rows x 40 bf16 (pad) = 10240 B; 4 tiles (Ah,Al,Bh,Bl) per stage.
#define TILE_B   10240
#define STAGE_B  40960
#define SMEM_DYN 81920
#define LDT      40      // padded row length in bf16 elems

__global__ __launch_bounds__(256, 2) void k_gemm_mma(const float* __restrict__ b2) {
    extern __shared__ char sm[];
    uint32_t smb = smem_u32(sm);
    int tid = threadIdx.x;
    int wid = tid >> 5, lane = tid & 31;
    int wm = wid >> 2, wn = wid & 3;            // warp grid 2(m) x 4(n), warp tile 64x32

    // L2-friendly swizzle: 8 strips of (64 rows x 8 col-tiles)
    int bid = blockIdx.x;
    int rt = (bid & 511) >> 3;                  // 0..63
    int ct = ((bid >> 9) << 3) | (bid & 7);     // 0..63
    int row0 = rt * 128, col0 = ct * 128;

    float c[4][4][4];
#pragma unroll
    for (int i = 0; i < 4; i++)
#pragma unroll
        for (int j = 0; j < 4; j++)
#pragma unroll
            for (int q = 0; q < 4; q++) c[i][j][q] = 0.f;

    // stage loader: 8 cp.async per thread
    auto load_stage = [&](int s, int st) {
        uint32_t sb = smb + st * STAGE_B;
#pragma unroll
        for (int v = 0; v < 2; v++) {
            int f = tid + v * 256;              // 0..511
            int r = f >> 2, cq = f & 3;         // 4 x 16B per 64B row
            uint32_t soff = r * (LDT * 2) + cq * 16;
            size_t ga = ((size_t)(row0 + r) << 10) + (size_t)s * 64 + cq * 16;
            size_t gb = ((size_t)(col0 + r) << 10) + (size_t)s * 64 + cq * 16;
            CP16(sb + soff,              (const char*)g_Hh  + ga);
            CP16(sb + TILE_B + soff,     (const char*)g_Hl  + ga);
            CP16(sb + 2 * TILE_B + soff, (const char*)g_W2h + gb);
            CP16(sb + 3 * TILE_B + soff, (const char*)g_W2l + gb);
        }
    };

    load_stage(0, 0);
    CP_COMMIT();

    for (int s = 0; s < 16; s++) {
        if (s < 15) { load_stage(s + 1, (s + 1) & 1); CP_COMMIT(); CP_WAIT1(); }
        else        { CP_WAIT0(); }
        __syncthreads();

        uint32_t base = smb + (s & 1) * STAGE_B;
#pragma unroll
        for (int ks = 0; ks < 2; ks++) {
            uint32_t a[4][4], bh[2][4], bl[2][4];
            // A hi frags (4 m-tiles)
            {
                int arow = wm * 64 + (lane & 15);
                int ak = ks * 16 + ((lane >> 4) << 3);
                uint32_t aoff = base + (uint32_t)(arow * (LDT * 2) + ak * 2);
#pragma unroll
                for (int i = 0; i < 4; i++) ldsm4(a[i], aoff + i * 16 * (LDT * 2));
            }
            // B frags (hi and lo), 2 ldsm4 each covering 4 n-tiles
            {
                int g = lane >> 3, r = lane & 7;
                int bn = wn * 32 + ((g >> 1) << 3) + r;
                int bk = ks * 16 + ((g & 1) << 3);
                uint32_t boff = (uint32_t)(bn * (LDT * 2) + bk * 2);
#pragma unroll
                for (int j = 0; j < 2; j++) {
                    ldsm4(bh[j], base + 2 * TILE_B + boff + j * 16 * (LDT * 2));
                    ldsm4(bl[j], base + 3 * TILE_B + boff + j * 16 * (LDT * 2));
                }
            }
            // pass 1: Ah*Bh ; pass 2: Ah*Bl
#pragma unroll
            for (int i = 0; i < 4; i++) {
#pragma unroll
                for (int jj = 0; jj < 4; jj++)
                    mma16816(c[i][jj], a[i], &bh[jj >> 1][(jj & 1) * 2]);
#pragma unroll
                for (int jj = 0; jj < 4; jj++)
                    mma16816(c[i][jj], a[i], &bl[jj >> 1][(jj & 1) * 2]);
            }
            // pass 3: Al*Bh  (reload a <- Al)
            {
                int arow = wm * 64 + (lane & 15);
                int ak = ks * 16 + ((lane >> 4) << 3);
                uint32_t aoff = base + TILE_B + (uint32_t)(arow * (LDT * 2) + ak * 2);
#pragma unroll
                for (int i = 0; i < 4; i++) ldsm4(a[i], aoff + i * 16 * (LDT * 2));
            }
#pragma unroll
            for (int i = 0; i < 4; i++)
#pragma unroll
                for (int jj = 0; jj < 4; jj++)
                    mma16816(c[i][jj], a[i], &bh[jj >> 1][(jj & 1) * 2]);
        }
        __syncthreads();
    }

    // ---- epilogue: stage accums in smem (stride 130), bias+relu+exp, coalesced writes ----
    float* eb = (float*)sm;                      // 128 x 130 floats = 66560 B
    float* red = (float*)(sm + 66560);           // 2 x 128 floats
#pragma unroll
    for (int i = 0; i < 4; i++) {
#pragma unroll
        for (int jj = 0; jj < 4; jj++) {
            int r = wm * 64 + i * 16 + (lane >> 2);
            int cc = wn * 32 + jj * 8 + (lane & 3) * 2;
            *(float2*)&eb[r * 130 + cc]       = make_float2(c[i][jj][0], c[i][jj][1]);
            *(float2*)&eb[(r + 8) * 130 + cc] = make_float2(c[i][jj][2], c[i][jj][3]);
        }
    }
    __syncthreads();
    {
        int col = tid & 127, half = tid >> 7;
        float bias = b2[col0 + col];
        float csum = 0.f;
        size_t gbase = (size_t)(row0 + half * 64) * Ee + col0 + col;
#pragma unroll 8
        for (int r = 0; r < 64; r++) {
            float v = __expf(fmaxf(eb[(half * 64 + r) * 130 + col] + bias, 0.0f));
            csum += v;
            g_E[gbase + (size_t)r * Ee] = v;
        }
        red[half * 128 + col] = csum;
    }
    __syncthreads();
    if (tid < 128)
        g_Zpart[(size_t)rt * Ee + col0 + tid] = red[tid] + red[128 + tid];
}

// ======================= K2b: softmax denominators =======================
__global__ void k_zreduce() {
    int idx = blockIdx.x * blockDim.x + threadIdx.x;
    int b = idx >> 13;
    int e = idx & (Ee - 1);
    float s = 0.f;
#pragma unroll
    for (int i = 0; i < 8; i++) s += g_Zpart[(size_t)(b * 8 + i) * Ee + e];
    g_Zinv[idx] = 1.0f / s;
}

// ======================= K3: normalize * xp, transpose, avgpool =======================
__global__ void k_final(const float* __restrict__ x, float* __restrict__ out) {
    int row = blockIdx.x;
    int b = row >> 10;
    __shared__ float t[Pp * 514];
    __shared__ float xs[Pp];
    int tid = threadIdx.x;
    if (tid < Pp) xs[tid] = x[row * Pp + tid] * (1.0f / 3.0f);
    const float* Erow = g_E + (size_t)row * Ee;
    const float* Zb = g_Zinv + b * Ee;
#pragma unroll
    for (int e = tid; e < Ee; e += 512) {
        float v = Erow[e] * Zb[e];
        int d = e >> 4, p = e & 15;
        t[p * 514 + d] = v;
    }
    __syncthreads();
    int d = tid;
    size_t obase = ((size_t)row * Pp) * Dd + d;
#pragma unroll
    for (int p = 0; p < Pp; p++) {
        const float* tp = t + p * 514;
        float cc = tp[d];
        float l = (d > 0)   ? tp[d - 1] : 0.f;
        float r = (d < 511) ? tp[d + 1] : 0.f;
        out[obase + (size_t)p * Dd] = xs[p] * (l + cc + r);
    }
}

// ======================= launch =======================
extern "C" void kernel_launch(void* const* d_in, const int* in_sizes, int n_in,
                              void* d_out, int out_size) {
    const float* x  = (const float*)d_in[0];
    const float* W1 = (const float*)d_in[1];
    const float* b1 = (const float*)d_in[2];
    const float* W2 = (const float*)d_in[3];
    const float* b2 = (const float*)d_in[4];
    float* out = (float*)d_out;

    static int smem_set = 0;
    if (!smem_set) {
        cudaFuncSetAttribute(k_gemm_mma, cudaFuncAttributeMaxDynamicSharedMemorySize, SMEM_DYN);
        smem_set = 1;
    }

    k_hidden<<<Mm, Dd>>>(x, W1, b1);
    k_w2conv<<<dim3(Ee / 64, Dd / 64), 256>>>(W2);
    k_gemm_mma<<<4096, 256, SMEM_DYN>>>(b2);
    k_zreduce<<<(Bsz * Ee) / 256, 256>>>();
    k_final<<<Mm, 512>>>(x, out);
}

// round 4
// speedup vs baseline: 2.9209x; 1.3029x over previous
#include <cuda_runtime.h>
#include <cuda_bf16.h>
#include <cstdint>

#define Bsz 8
#define Pp  16
#define Dd  512
#define Ee  8192
#define Mm  8192
#define LOG2E 1.4426950408889634f

// Scratch (device globals)
__device__ __nv_bfloat16 g_Hh[(size_t)Mm * Dd];   // bf16(H), row-major [M][512]
__device__ __nv_bfloat16 g_W2h[(size_t)Ee * Dd];  // hi of (W2*log2e)^T, [E][512]
__device__ __nv_bfloat16 g_W2l[(size_t)Ee * Dd];  // lo
__device__ float g_E[(size_t)Mm * Ee];            // 256 MB exp(relu(logits))
__device__ float g_Zpart[64 * Ee];
__device__ float g_Zinv[Bsz * Ee];

// ======================= PTX helpers =======================
__device__ __forceinline__ uint32_t smem_u32(const void* p) {
    uint32_t a;
    asm("{ .reg .u64 t; cvta.to.shared.u64 t, %1; cvt.u32.u64 %0, t; }" : "=r"(a) : "l"(p));
    return a;
}
#define CP16(dst, src) \
    asm volatile("cp.async.cg.shared.global [%0], [%1], 16;" :: "r"(dst), "l"(src) : "memory")
#define CP_COMMIT() asm volatile("cp.async.commit_group;" ::: "memory")
#define CP_WAIT(n)  asm volatile("cp.async.wait_group %0;" :: "n"(n) : "memory")

__device__ __forceinline__ void ldsm4(uint32_t* r, uint32_t addr) {
    asm volatile("ldmatrix.sync.aligned.m8n8.x4.shared.b16 {%0,%1,%2,%3}, [%4];"
                 : "=r"(r[0]), "=r"(r[1]), "=r"(r[2]), "=r"(r[3]) : "r"(addr));
}
__device__ __forceinline__ void mma16816(float* c, const uint32_t* a, const uint32_t* b) {
    asm volatile("mma.sync.aligned.m16n8k16.row.col.f32.bf16.bf16.f32 "
                 "{%0,%1,%2,%3}, {%4,%5,%6,%7}, {%8,%9}, {%0,%1,%2,%3};"
                 : "+f"(c[0]), "+f"(c[1]), "+f"(c[2]), "+f"(c[3])
                 : "r"(a[0]), "r"(a[1]), "r"(a[2]), "r"(a[3]), "r"(b[0]), "r"(b[1]));
}
__device__ __forceinline__ float ex2f(float x) {
    float r;
    asm("ex2.approx.ftz.f32 %0, %1;" : "=f"(r) : "f"(x));
    return r;
}

// ======================= K1: hidden layer -> bf16 =======================
__global__ void k_hidden(const float* __restrict__ x,
                         const float* __restrict__ W1,
                         const float* __restrict__ b1) {
    int row = blockIdx.x;
    __shared__ float xs[Pp];
    int tid = threadIdx.x;                  // = d (512 threads)
    if (tid < Pp) xs[tid] = x[row * Pp + tid];
    __syncthreads();
    float acc = b1[tid];
#pragma unroll
    for (int p = 0; p < Pp; p++) acc = fmaf(xs[p], W1[p * Dd + tid], acc);
    g_Hh[(size_t)row * Dd + tid] = __float2bfloat16(fmaxf(acc, 0.0f));
}

// ======================= K1b: W2 * log2e, transpose + bf16 split =======================
__global__ void k_w2conv(const float* __restrict__ W2) {
    __shared__ float ts[64][65];
    int e0 = blockIdx.x * 64, k0 = blockIdx.y * 64;
    int tid = threadIdx.x;
#pragma unroll
    for (int idx = tid; idx < 4096; idx += 256) {
        int i = idx >> 6, j = idx & 63;     // i=k, j=e
        ts[i][j] = W2[(size_t)(k0 + i) * Ee + e0 + j] * LOG2E;
    }
    __syncthreads();
#pragma unroll
    for (int idx = tid; idx < 4096; idx += 256) {
        int j = idx >> 6, i = idx & 63;     // j=e, i=k
        float v = ts[i][j];
        __nv_bfloat16 hh = __float2bfloat16(v);
        float lo = v - __bfloat162float(hh);
        size_t o = (size_t)(e0 + j) * Dd + k0 + i;
        g_W2h[o] = hh;
        g_W2l[o] = __float2bfloat16(lo);
    }
}

// ======================= K2: mma.sync 2-pass GEMM + fused epilogue =======================
// CTA 128x128, BK=32, 16 K-stages, 3-deep cp.async pipeline.
// Stage: Ah | Bh | Bl, each 128 rows x 40 bf16 (80B padded) = 10240 B.
#define TILE_B   10240
#define STAGE_B  30720
#define NSTG     3
#define SMEM_DYN (NSTG * STAGE_B)          // 92160 (epilogue reuses: needs 67584)
#define LDT      40

__global__ __launch_bounds__(256, 2) void k_gemm_mma(const float* __restrict__ b2) {
    extern __shared__ char sm[];
    uint32_t smb = smem_u32(sm);
    int tid = threadIdx.x;
    int wid = tid >> 5, lane = tid & 31;
    int wm = wid >> 2, wn = wid & 3;            // warp grid 2(m) x 4(n), warp tile 64x32

    // L2-friendly swizzle: strips of (64 row-tiles x 8 col-tiles)
    int bid = blockIdx.x;
    int rt = (bid & 511) >> 3;
    int ct = ((bid >> 9) << 3) | (bid & 7);
    int row0 = rt * 128, col0 = ct * 128;

    float c[4][4][4];
#pragma unroll
    for (int i = 0; i < 4; i++)
#pragma unroll
        for (int j = 0; j < 4; j++)
#pragma unroll
            for (int q = 0; q < 4; q++) c[i][j][q] = 0.f;

    // stage loader: 6 cp16 per thread
    auto load_stage = [&](int s, int st) {
        uint32_t sb = smb + st * STAGE_B;
#pragma unroll
        for (int v = 0; v < 2; v++) {
            int f = tid + v * 256;              // 0..511
            int r = f >> 2, cq = f & 3;
            uint32_t soff = r * (LDT * 2) + cq * 16;
            size_t ga = ((size_t)(row0 + r) << 10) + (size_t)s * 64 + cq * 16;
            size_t gb = ((size_t)(col0 + r) << 10) + (size_t)s * 64 + cq * 16;
            CP16(sb + soff,              (const char*)g_Hh  + ga);
            CP16(sb + TILE_B + soff,     (const char*)g_W2h + gb);
            CP16(sb + 2 * TILE_B + soff, (const char*)g_W2l + gb);
        }
    };

    load_stage(0, 0); CP_COMMIT();
    load_stage(1, 1); CP_COMMIT();

    for (int s = 0; s < 16; s++) {
        if (s + 2 < 16) { load_stage(s + 2, (s + 2) % NSTG); CP_COMMIT(); }
        if (s < 14)      CP_WAIT(2);
        else if (s < 15) CP_WAIT(1);
        else             CP_WAIT(0);
        __syncthreads();

        uint32_t base = smb + (s % NSTG) * STAGE_B;
#pragma unroll
        for (int ks = 0; ks < 2; ks++) {
            uint32_t a[4][4], bh[2][4], bl[2][4];
            {
                int arow = wm * 64 + (lane & 15);
                int ak = ks * 16 + ((lane >> 4) << 3);
                uint32_t aoff = base + (uint32_t)(arow * (LDT * 2) + ak * 2);
#pragma unroll
                for (int i = 0; i < 4; i++) ldsm4(a[i], aoff + i * 16 * (LDT * 2));
            }
            {
                int g = lane >> 3, r = lane & 7;
                int bn = wn * 32 + ((g >> 1) << 3) + r;
                int bk = ks * 16 + ((g & 1) << 3);
                uint32_t boff = (uint32_t)(bn * (LDT * 2) + bk * 2);
#pragma unroll
                for (int j = 0; j < 2; j++) {
                    ldsm4(bh[j], base + TILE_B + boff + j * 16 * (LDT * 2));
                    ldsm4(bl[j], base + 2 * TILE_B + boff + j * 16 * (LDT * 2));
                }
            }
#pragma unroll
            for (int i = 0; i < 4; i++) {
#pragma unroll
                for (int jj = 0; jj < 4; jj++)
                    mma16816(c[i][jj], a[i], &bh[jj >> 1][(jj & 1) * 2]);
#pragma unroll
                for (int jj = 0; jj < 4; jj++)
                    mma16816(c[i][jj], a[i], &bl[jj >> 1][(jj & 1) * 2]);
            }
        }
        __syncthreads();
    }

    // ---- epilogue: stage in smem (stride 130), bias + relu + ex2, coalesced writes ----
    float* eb = (float*)sm;                      // 128 x 130 floats = 66560 B
    float* red = (float*)(sm + 66560);           // 2 x 128 floats
#pragma unroll
    for (int i = 0; i < 4; i++) {
#pragma unroll
        for (int jj = 0; jj < 4; jj++) {
            int r = wm * 64 + i * 16 + (lane >> 2);
            int cc = wn * 32 + jj * 8 + (lane & 3) * 2;
            *(float2*)&eb[r * 130 + cc]       = make_float2(c[i][jj][0], c[i][jj][1]);
            *(float2*)&eb[(r + 8) * 130 + cc] = make_float2(c[i][jj][2], c[i][jj][3]);
        }
    }
    __syncthreads();
    {
        int col = tid & 127, half = tid >> 7;
        float bias = b2[col0 + col] * LOG2E;
        float csum = 0.f;
        size_t gbase = (size_t)(row0 + half * 64) * Ee + col0 + col;
#pragma unroll 8
        for (int r = 0; r < 64; r++) {
            float v = ex2f(fmaxf(eb[(half * 64 + r) * 130 + col] + bias, 0.0f));
            csum += v;
            g_E[gbase + (size_t)r * Ee] = v;
        }
        red[half * 128 + col] = csum;
    }
    __syncthreads();
    if (tid < 128)
        g_Zpart[(size_t)rt * Ee + col0 + tid] = red[tid] + red[128 + tid];
}

// ======================= K2b: softmax denominators =======================
__global__ void k_zreduce() {
    int idx = blockIdx.x * blockDim.x + threadIdx.x;
    int b = idx >> 13;
    int e = idx & (Ee - 1);
    float s = 0.f;
#pragma unroll
    for (int i = 0; i < 8; i++) s += g_Zpart[(size_t)(b * 8 + i) * Ee + e];
    g_Zinv[idx] = 1.0f / s;
}

// ======================= K3: normalize * xp, transpose, avgpool =======================
__global__ void k_final(const float* __restrict__ x, float* __restrict__ out) {
    int row = blockIdx.x;
    int b = row >> 10;
    __shared__ float t[Pp * 514];
    __shared__ float xs[Pp];
    int tid = threadIdx.x;
    if (tid < Pp) xs[tid] = x[row * Pp + tid] * (1.0f / 3.0f);
    const float4* E4 = (const float4*)(g_E + (size_t)row * Ee);
    const float4* Z4 = (const float4*)(g_Zinv + (size_t)b * Ee);
#pragma unroll
    for (int i = 0; i < 4; i++) {
        int idx4 = i * 512 + tid;
        float4 e = E4[idx4], z = Z4[idx4];
        int d = idx4 >> 2, p0 = (idx4 & 3) * 4;
        t[(p0 + 0) * 514 + d] = e.x * z.x;
        t[(p0 + 1) * 514 + d] = e.y * z.y;
        t[(p0 + 2) * 514 + d] = e.z * z.z;
        t[(p0 + 3) * 514 + d] = e.w * z.w;
    }
    __syncthreads();
    int d = tid;
    size_t obase = ((size_t)row * Pp) * Dd + d;
#pragma unroll
    for (int p = 0; p < Pp; p++) {
        const float* tp = t + p * 514;
        float cc = tp[d];
        float l = (d > 0)   ? tp[d - 1] : 0.f;
        float r = (d < 511) ? tp[d + 1] : 0.f;
        out[obase + (size_t)p * Dd] = xs[p] * (l + cc + r);
    }
}

// ======================= launch =======================
extern "C" void kernel_launch(void* const* d_in, const int* in_sizes, int n_in,
                              void* d_out, int out_size) {
    const float* x  = (const float*)d_in[0];
    const float* W1 = (const float*)d_in[1];
    const float* b1 = (const float*)d_in[2];
    const float* W2 = (const float*)d_in[3];
    const float* b2 = (const float*)d_in[4];
    float* out = (float*)d_out;

    static int smem_set = 0;
    if (!smem_set) {
        cudaFuncSetAttribute(k_gemm_mma, cudaFuncAttributeMaxDynamicSharedMemorySize, SMEM_DYN);
        smem_set = 1;
    }

    k_hidden<<<Mm, Dd>>>(x, W1, b1);
    k_w2conv<<<dim3(Ee / 64, Dd / 64), 256>>>(W2);
    k_gemm_mma<<<4096, 256, SMEM_DYN>>>(b2);
    k_zreduce<<<(Bsz * Ee) / 256, 256>>>();
    k_final<<<Mm, 512>>>(x, out);
}

// round 5
// speedup vs baseline: 4.0318x; 1.3803x over previous
#include <cuda_runtime.h>
#include <cuda_fp16.h>
#include <cstdint>

#define Bsz 8
#define Pp  16
#define Dd  512
#define Ee  8192
#define Mm  8192
#define LOG2E 1.4426950408889634f

// Scratch (device globals)
__device__ __half g_Hh[(size_t)Mm * Dd];    // fp16(H), row-major [M][512]
__device__ __half g_W2h[(size_t)Ee * Dd];   // fp16 of (W2*log2e)^T, [E][512]
__device__ float g_E[(size_t)Mm * Ee];      // 256 MB exp(relu(logits))
__device__ float g_Zpart[64 * Ee];
__device__ float g_Zinv[Bsz * Ee];

// ======================= PTX helpers =======================
__device__ __forceinline__ uint32_t smem_u32(const void* p) {
    uint32_t a;
    asm("{ .reg .u64 t; cvta.to.shared.u64 t, %1; cvt.u32.u64 %0, t; }" : "=r"(a) : "l"(p));
    return a;
}
#define CP16(dst, src) \
    asm volatile("cp.async.cg.shared.global [%0], [%1], 16;" :: "r"(dst), "l"(src) : "memory")
#define CP_COMMIT() asm volatile("cp.async.commit_group;" ::: "memory")
#define CP_WAIT(n)  asm volatile("cp.async.wait_group %0;" :: "n"(n) : "memory")

__device__ __forceinline__ void ldsm4(uint32_t* r, uint32_t addr) {
    asm volatile("ldmatrix.sync.aligned.m8n8.x4.shared.b16 {%0,%1,%2,%3}, [%4];"
                 : "=r"(r[0]), "=r"(r[1]), "=r"(r[2]), "=r"(r[3]) : "r"(addr));
}
__device__ __forceinline__ void mma16816(float* c, const uint32_t* a, const uint32_t* b) {
    asm volatile("mma.sync.aligned.m16n8k16.row.col.f32.f16.f16.f32 "
                 "{%0,%1,%2,%3}, {%4,%5,%6,%7}, {%8,%9}, {%0,%1,%2,%3};"
                 : "+f"(c[0]), "+f"(c[1]), "+f"(c[2]), "+f"(c[3])
                 : "r"(a[0]), "r"(a[1]), "r"(a[2]), "r"(a[3]), "r"(b[0]), "r"(b[1]));
}
__device__ __forceinline__ float ex2f(float x) {
    float r;
    asm("ex2.approx.ftz.f32 %0, %1;" : "=f"(r) : "f"(x));
    return r;
}

// ======================= K1: hidden layer -> fp16 =======================
__global__ void k_hidden(const float* __restrict__ x,
                         const float* __restrict__ W1,
                         const float* __restrict__ b1) {
    int row = blockIdx.x;
    __shared__ float xs[Pp];
    int tid = threadIdx.x;                  // = d (512 threads)
    if (tid < Pp) xs[tid] = x[row * Pp + tid];
    __syncthreads();
    float acc = b1[tid];
#pragma unroll
    for (int p = 0; p < Pp; p++) acc = fmaf(xs[p], W1[p * Dd + tid], acc);
    g_Hh[(size_t)row * Dd + tid] = __float2half(fmaxf(acc, 0.0f));
}

// ======================= K1b: W2 * log2e, transpose -> fp16 =======================
__global__ void k_w2conv(const float* __restrict__ W2) {
    __shared__ float ts[64][65];
    int e0 = blockIdx.x * 64, k0 = blockIdx.y * 64;
    int tid = threadIdx.x;
#pragma unroll
    for (int idx = tid; idx < 4096; idx += 256) {
        int i = idx >> 6, j = idx & 63;     // i=k, j=e
        ts[i][j] = W2[(size_t)(k0 + i) * Ee + e0 + j] * LOG2E;
    }
    __syncthreads();
#pragma unroll
    for (int idx = tid; idx < 4096; idx += 256) {
        int j = idx >> 6, i = idx & 63;     // j=e, i=k
        g_W2h[(size_t)(e0 + j) * Dd + k0 + i] = __float2half(ts[i][j]);
    }
}

// ======================= K2: mma.sync fp16 GEMM + fused epilogue =======================
// CTA 128x128, BK=32, 16 K-stages, 4-deep cp.async pipeline.
// Stage: A | B, each 128 rows x 40 fp16 (80B padded) = 10240 B.
#define TILE_B   10240
#define STAGE_B  20480
#define NSTG     4
#define SMEM_DYN (NSTG * STAGE_B)          // 81920 (epilogue reuses: needs 67584)
#define LDT      40

__global__ __launch_bounds__(256, 2) void k_gemm_mma(const float* __restrict__ b2) {
    extern __shared__ char sm[];
    uint32_t smb = smem_u32(sm);
    int tid = threadIdx.x;
    int wid = tid >> 5, lane = tid & 31;
    int wm = wid >> 2, wn = wid & 3;            // warp grid 2(m) x 4(n), warp tile 64x32

    // L2-friendly swizzle: strips of (64 row-tiles x 8 col-tiles)
    int bid = blockIdx.x;
    int rt = (bid & 511) >> 3;
    int ct = ((bid >> 9) << 3) | (bid & 7);
    int row0 = rt * 128, col0 = ct * 128;

    float c[4][4][4];
#pragma unroll
    for (int i = 0; i < 4; i++)
#pragma unroll
        for (int j = 0; j < 4; j++)
#pragma unroll
            for (int q = 0; q < 4; q++) c[i][j][q] = 0.f;

    // stage loader: 4 cp16 per thread
    auto load_stage = [&](int s, int st) {
        uint32_t sb = smb + st * STAGE_B;
#pragma unroll
        for (int v = 0; v < 2; v++) {
            int f = tid + v * 256;              // 0..511
            int r = f >> 2, cq = f & 3;
            uint32_t soff = r * (LDT * 2) + cq * 16;
            size_t ga = ((size_t)(row0 + r) << 10) + (size_t)s * 64 + cq * 16;
            size_t gb = ((size_t)(col0 + r) << 10) + (size_t)s * 64 + cq * 16;
            CP16(sb + soff,          (const char*)g_Hh  + ga);
            CP16(sb + TILE_B + soff, (const char*)g_W2h + gb);
        }
    };

    load_stage(0, 0); CP_COMMIT();
    load_stage(1, 1); CP_COMMIT();
    load_stage(2, 2); CP_COMMIT();

    for (int s = 0; s < 16; s++) {
        if (s + 3 < 16) { load_stage(s + 3, (s + 3) & (NSTG - 1)); CP_COMMIT(); }
        if (s < 13)      CP_WAIT(3);
        else if (s < 14) CP_WAIT(2);
        else if (s < 15) CP_WAIT(1);
        else             CP_WAIT(0);
        __syncthreads();

        uint32_t base = smb + (s & (NSTG - 1)) * STAGE_B;
#pragma unroll
        for (int ks = 0; ks < 2; ks++) {
            uint32_t a[4][4], bh[2][4];
            {
                int arow = wm * 64 + (lane & 15);
                int ak = ks * 16 + ((lane >> 4) << 3);
                uint32_t aoff = base + (uint32_t)(arow * (LDT * 2) + ak * 2);
#pragma unroll
                for (int i = 0; i < 4; i++) ldsm4(a[i], aoff + i * 16 * (LDT * 2));
            }
            {
                int g = lane >> 3, r = lane & 7;
                int bn = wn * 32 + ((g >> 1) << 3) + r;
                int bk = ks * 16 + ((g & 1) << 3);
                uint32_t boff = base + TILE_B + (uint32_t)(bn * (LDT * 2) + bk * 2);
#pragma unroll
                for (int j = 0; j < 2; j++)
                    ldsm4(bh[j], boff + j * 16 * (LDT * 2));
            }
#pragma unroll
            for (int i = 0; i < 4; i++)
#pragma unroll
                for (int jj = 0; jj < 4; jj++)
                    mma16816(c[i][jj], a[i], &bh[jj >> 1][(jj & 1) * 2]);
        }
        __syncthreads();
    }

    // ---- epilogue: stage in smem (stride 130), bias + relu + ex2, coalesced writes ----
    float* eb = (float*)sm;                      // 128 x 130 floats = 66560 B
    float* red = (float*)(sm + 66560);           // 2 x 128 floats
#pragma unroll
    for (int i = 0; i < 4; i++) {
#pragma unroll
        for (int jj = 0; jj < 4; jj++) {
            int r = wm * 64 + i * 16 + (lane >> 2);
            int cc = wn * 32 + jj * 8 + (lane & 3) * 2;
            *(float2*)&eb[r * 130 + cc]       = make_float2(c[i][jj][0], c[i][jj][1]);
            *(float2*)&eb[(r + 8) * 130 + cc] = make_float2(c[i][jj][2], c[i][jj][3]);
        }
    }
    __syncthreads();
    {
        int col = tid & 127, half = tid >> 7;
        float bias = b2[col0 + col] * LOG2E;
        float csum = 0.f;
        size_t gbase = (size_t)(row0 + half * 64) * Ee + col0 + col;
#pragma unroll 8
        for (int r = 0; r < 64; r++) {
            float v = ex2f(fmaxf(eb[(half * 64 + r) * 130 + col] + bias, 0.0f));
            csum += v;
            g_E[gbase + (size_t)r * Ee] = v;
        }
        red[half * 128 + col] = csum;
    }
    __syncthreads();
    if (tid < 128)
        g_Zpart[(size_t)rt * Ee + col0 + tid] = red[tid] + red[128 + tid];
}

// ======================= K2b: softmax denominators =======================
__global__ void k_zreduce() {
    int idx = blockIdx.x * blockDim.x + threadIdx.x;
    int b = idx >> 13;
    int e = idx & (Ee - 1);
    float s = 0.f;
#pragma unroll
    for (int i = 0; i < 8; i++) s += g_Zpart[(size_t)(b * 8 + i) * Ee + e];
    g_Zinv[idx] = 1.0f / s;
}

// ======================= K3: normalize * xp, transpose, avgpool =======================
__global__ void k_final(const float* __restrict__ x, float* __restrict__ out) {
    int row = blockIdx.x;
    int b = row >> 10;
    __shared__ float t[Pp * 514];
    __shared__ float xs[Pp];
    int tid = threadIdx.x;
    if (tid < Pp) xs[tid] = x[row * Pp + tid] * (1.0f / 3.0f);
    const float4* E4 = (const float4*)(g_E + (size_t)row * Ee);
    const float4* Z4 = (const float4*)(g_Zinv + (size_t)b * Ee);
#pragma unroll
    for (int i = 0; i < 4; i++) {
        int idx4 = i * 512 + tid;
        float4 e = E4[idx4], z = Z4[idx4];
        int d = idx4 >> 2, p0 = (idx4 & 3) * 4;
        t[(p0 + 0) * 514 + d] = e.x * z.x;
        t[(p0 + 1) * 514 + d] = e.y * z.y;
        t[(p0 + 2) * 514 + d] = e.z * z.z;
        t[(p0 + 3) * 514 + d] = e.w * z.w;
    }
    __syncthreads();
    int d = tid;
    size_t obase = ((size_t)row * Pp) * Dd + d;
#pragma unroll
    for (int p = 0; p < Pp; p++) {
        const float* tp = t + p * 514;
        float cc = tp[d];
        float l = (d > 0)   ? tp[d - 1] : 0.f;
        float r = (d < 511) ? tp[d + 1] : 0.f;
        out[obase + (size_t)p * Dd] = xs[p] * (l + cc + r);
    }
}

// ======================= launch =======================
extern "C" void kernel_launch(void* const* d_in, const int* in_sizes, int n_in,
                              void* d_out, int out_size) {
    const float* x  = (const float*)d_in[0];
    const float* W1 = (const float*)d_in[1];
    const float* b1 = (const float*)d_in[2];
    const float* W2 = (const float*)d_in[3];
    const float* b2 = (const float*)d_in[4];
    float* out = (float*)d_out;

    static int smem_set = 0;
    if (!smem_set) {
        cudaFuncSetAttribute(k_gemm_mma, cudaFuncAttributeMaxDynamicSharedMemorySize, SMEM_DYN);
        smem_set = 1;
    }

    k_hidden<<<Mm, Dd>>>(x, W1, b1);
    k_w2conv<<<dim3(Ee / 64, Dd / 64), 256>>>(W2);
    k_gemm_mma<<<4096, 256, SMEM_DYN>>>(b2);
    k_zreduce<<<(Bsz * Ee) / 256, 256>>>();
    k_final<<<Mm, 512>>>(x, out);
}

// round 6
// speedup vs baseline: 4.0965x; 1.0160x over previous
#include <cuda_runtime.h>
#include <cuda_fp16.h>
#include <cstdint>

#define Bsz 8
#define Pp  16
#define Dd  512
#define Ee  8192
#define Mm  8192
#define LOG2E 1.4426950408889634f

// Scratch (device globals)
__device__ __half g_Hh[(size_t)Mm * Dd];    // fp16(H), row-major [M][512]
__device__ __half g_W2h[(size_t)Ee * Dd];   // fp16 of (W2*log2e)^T, [E][512]
__device__ __half g_E[(size_t)Mm * Ee];     // 128 MB exp(relu(logits)) in fp16
__device__ float g_Zpart[64 * Ee];
__device__ float g_Zinv[Bsz * Ee];

// ======================= PTX helpers =======================
__device__ __forceinline__ uint32_t smem_u32(const void* p) {
    uint32_t a;
    asm("{ .reg .u64 t; cvta.to.shared.u64 t, %1; cvt.u32.u64 %0, t; }" : "=r"(a) : "l"(p));
    return a;
}
#define CP16(dst, src) \
    asm volatile("cp.async.cg.shared.global [%0], [%1], 16;" :: "r"(dst), "l"(src) : "memory")
#define CP_COMMIT() asm volatile("cp.async.commit_group;" ::: "memory")
#define CP_WAIT(n)  asm volatile("cp.async.wait_group %0;" :: "n"(n) : "memory")

__device__ __forceinline__ void ldsm4(uint32_t* r, uint32_t addr) {
    asm volatile("ldmatrix.sync.aligned.m8n8.x4.shared.b16 {%0,%1,%2,%3}, [%4];"
                 : "=r"(r[0]), "=r"(r[1]), "=r"(r[2]), "=r"(r[3]) : "r"(addr));
}
__device__ __forceinline__ void mma16816(float* c, const uint32_t* a, const uint32_t* b) {
    asm volatile("mma.sync.aligned.m16n8k16.row.col.f32.f16.f16.f32 "
                 "{%0,%1,%2,%3}, {%4,%5,%6,%7}, {%8,%9}, {%0,%1,%2,%3};"
                 : "+f"(c[0]), "+f"(c[1]), "+f"(c[2]), "+f"(c[3])
                 : "r"(a[0]), "r"(a[1]), "r"(a[2]), "r"(a[3]), "r"(b[0]), "r"(b[1]));
}
__device__ __forceinline__ float ex2f(float x) {
    float r;
    asm("ex2.approx.ftz.f32 %0, %1;" : "=f"(r) : "f"(x));
    return r;
}

// ======================= K1: hidden layer -> fp16 =======================
__global__ void k_hidden(const float* __restrict__ x,
                         const float* __restrict__ W1,
                         const float* __restrict__ b1) {
    int row = blockIdx.x;
    __shared__ float xs[Pp];
    int tid = threadIdx.x;                  // = d (512 threads)
    if (tid < Pp) xs[tid] = x[row * Pp + tid];
    __syncthreads();
    float acc = b1[tid];
#pragma unroll
    for (int p = 0; p < Pp; p++) acc = fmaf(xs[p], W1[p * Dd + tid], acc);
    g_Hh[(size_t)row * Dd + tid] = __float2half(fmaxf(acc, 0.0f));
}

// ======================= K1b: W2 * log2e, transpose -> fp16 =======================
__global__ void k_w2conv(const float* __restrict__ W2) {
    __shared__ float ts[64][65];
    int e0 = blockIdx.x * 64, k0 = blockIdx.y * 64;
    int tid = threadIdx.x;
#pragma unroll
    for (int idx = tid; idx < 4096; idx += 256) {
        int i = idx >> 6, j = idx & 63;     // i=k, j=e
        ts[i][j] = W2[(size_t)(k0 + i) * Ee + e0 + j] * LOG2E;
    }
    __syncthreads();
#pragma unroll
    for (int idx = tid; idx < 4096; idx += 256) {
        int j = idx >> 6, i = idx & 63;     // j=e, i=k
        g_W2h[(size_t)(e0 + j) * Dd + k0 + i] = __float2half(ts[i][j]);
    }
}

// ======================= K2: mma.sync fp16 GEMM + fused epilogue =======================
// CTA 128x128, BK=32, 16 K-stages, 5-stage cp.async ring, ONE sync per stage.
#define TILE_B   10240
#define STAGE_B  20480
#define NSTG     5
#define SMEM_DYN (NSTG * STAGE_B)          // 102400 ; epilogue reuses first 67584 B
#define LDT      40

__global__ __launch_bounds__(256, 2) void k_gemm_mma(const float* __restrict__ b2) {
    extern __shared__ char sm[];
    uint32_t smb = smem_u32(sm);
    int tid = threadIdx.x;
    int wid = tid >> 5, lane = tid & 31;
    int wm = wid >> 2, wn = wid & 3;            // warp grid 2(m) x 4(n), warp tile 64x32

    // L2-friendly swizzle: strips of (64 row-tiles x 8 col-tiles)
    int bid = blockIdx.x;
    int rt = (bid & 511) >> 3;
    int ct = ((bid >> 9) << 3) | (bid & 7);
    int row0 = rt * 128, col0 = ct * 128;

    float c[4][4][4];
#pragma unroll
    for (int i = 0; i < 4; i++)
#pragma unroll
        for (int j = 0; j < 4; j++)
#pragma unroll
            for (int q = 0; q < 4; q++) c[i][j][q] = 0.f;

    auto load_stage = [&](int s, int st) {
        uint32_t sb = smb + st * STAGE_B;
#pragma unroll
        for (int v = 0; v < 2; v++) {
            int f = tid + v * 256;              // 0..511
            int r = f >> 2, cq = f & 3;
            uint32_t soff = r * (LDT * 2) + cq * 16;
            size_t ga = ((size_t)(row0 + r) << 10) + (size_t)s * 64 + cq * 16;
            size_t gb = ((size_t)(col0 + r) << 10) + (size_t)s * 64 + cq * 16;
            CP16(sb + soff,          (const char*)g_Hh  + ga);
            CP16(sb + TILE_B + soff, (const char*)g_W2h + gb);
        }
    };

    load_stage(0, 0); CP_COMMIT();
    load_stage(1, 1); CP_COMMIT();
    load_stage(2, 2); CP_COMMIT();

    int bc = 0, bl = 3;
    for (int s = 0; s < 16; s++) {
        if (s + 3 < 16) {
            load_stage(s + 3, bl); CP_COMMIT();
            if (++bl == NSTG) bl = 0;
        }
        if (s < 13)      CP_WAIT(3);
        else if (s < 14) CP_WAIT(2);
        else if (s < 15) CP_WAIT(1);
        else             CP_WAIT(0);
        __syncthreads();

        uint32_t base = smb + bc * STAGE_B;
        if (++bc == NSTG) bc = 0;
#pragma unroll
        for (int ks = 0; ks < 2; ks++) {
            uint32_t a[4][4], bh[2][4];
            {
                int arow = wm * 64 + (lane & 15);
                int ak = ks * 16 + ((lane >> 4) << 3);
                uint32_t aoff = base + (uint32_t)(arow * (LDT * 2) + ak * 2);
#pragma unroll
                for (int i = 0; i < 4; i++) ldsm4(a[i], aoff + i * 16 * (LDT * 2));
            }
            {
                int g = lane >> 3, r = lane & 7;
                int bn = wn * 32 + ((g >> 1) << 3) + r;
                int bk = ks * 16 + ((g & 1) << 3);
                uint32_t boff = base + TILE_B + (uint32_t)(bn * (LDT * 2) + bk * 2);
#pragma unroll
                for (int j = 0; j < 2; j++)
                    ldsm4(bh[j], boff + j * 16 * (LDT * 2));
            }
#pragma unroll
            for (int i = 0; i < 4; i++)
#pragma unroll
                for (int jj = 0; jj < 4; jj++)
                    mma16816(c[i][jj], a[i], &bh[jj >> 1][(jj & 1) * 2]);
        }
    }
    __syncthreads();   // protect smem reuse by epilogue

    // ---- epilogue: stage in smem (stride 130), bias + relu + ex2, fp16 writes ----
    float* eb = (float*)sm;                      // 128 x 130 floats = 66560 B
    float* red = (float*)(sm + 66560);           // 2 x 128 floats
#pragma unroll
    for (int i = 0; i < 4; i++) {
#pragma unroll
        for (int jj = 0; jj < 4; jj++) {
            int r = wm * 64 + i * 16 + (lane >> 2);
            int cc = wn * 32 + jj * 8 + (lane & 3) * 2;
            *(float2*)&eb[r * 130 + cc]       = make_float2(c[i][jj][0], c[i][jj][1]);
            *(float2*)&eb[(r + 8) * 130 + cc] = make_float2(c[i][jj][2], c[i][jj][3]);
        }
    }
    __syncthreads();
    {
        int col = tid & 127, half = tid >> 7;
        float bias = b2[col0 + col] * LOG2E;
        float csum = 0.f;
        size_t gbase = (size_t)(row0 + half * 64) * Ee + col0 + col;
#pragma unroll 8
        for (int r = 0; r < 64; r++) {
            float v = ex2f(fmaxf(eb[(half * 64 + r) * 130 + col] + bias, 0.0f));
            csum += v;
            g_E[gbase + (size_t)r * Ee] = __float2half(v);
        }
        red[half * 128 + col] = csum;
    }
    __syncthreads();
    if (tid < 128)
        g_Zpart[(size_t)rt * Ee + col0 + tid] = red[tid] + red[128 + tid];
}

// ======================= K2b: softmax denominators =======================
__global__ void k_zreduce() {
    int idx = blockIdx.x * blockDim.x + threadIdx.x;
    int b = idx >> 13;
    int e = idx & (Ee - 1);
    float s = 0.f;
#pragma unroll
    for (int i = 0; i < 8; i++) s += g_Zpart[(size_t)(b * 8 + i) * Ee + e];
    g_Zinv[idx] = 1.0f / s;
}

// ======================= K3: normalize * xp, transpose, avgpool (4 rows/CTA) =======================
#define RPC 4
__global__ void k_final(const float* __restrict__ x, float* __restrict__ out) {
    int b = blockIdx.x >> 8;                 // 256 CTAs per batch
    int row0 = blockIdx.x * RPC;
    __shared__ float zs[Ee];                 // 32 KB: Zinv for this batch
    __shared__ float t[Pp * 514];            // 32.9 KB
    __shared__ float xs[Pp];
    int tid = threadIdx.x;                   // 512 threads

    {   // load Zinv[b,:] once
        const float4* Z4 = (const float4*)(g_Zinv + (size_t)b * Ee);
        float4* zs4 = (float4*)zs;
#pragma unroll
        for (int i = 0; i < 4; i++) zs4[i * 512 + tid] = Z4[i * 512 + tid];
    }

    for (int r = 0; r < RPC; r++) {
        int row = row0 + r;
        __syncthreads();
        if (tid < Pp) xs[tid] = x[row * Pp + tid] * (1.0f / 3.0f);
        const __half2* E2 = (const __half2*)(g_E + (size_t)row * Ee);
#pragma unroll
        for (int i = 0; i < 8; i++) {
            int idx2 = i * 512 + tid;        // half2 index: e = 2*idx2
            __half2 e2 = E2[idx2];
            int d = idx2 >> 3;
            int p0 = (idx2 & 7) * 2;
            int e = idx2 * 2;
            t[p0 * 514 + d]       = __low2float(e2)  * zs[e];
            t[(p0 + 1) * 514 + d] = __high2float(e2) * zs[e + 1];
        }
        __syncthreads();
        int d = tid;
        size_t obase = ((size_t)row * Pp) * Dd + d;
#pragma unroll
        for (int p = 0; p < Pp; p++) {
            const float* tp = t + p * 514;
            float cc = tp[d];
            float l = (d > 0)   ? tp[d - 1] : 0.f;
            float rr = (d < 511) ? tp[d + 1] : 0.f;
            out[obase + (size_t)p * Dd] = xs[p] * (l + cc + rr);
        }
    }
}

// ======================= launch =======================
extern "C" void kernel_launch(void* const* d_in, const int* in_sizes, int n_in,
                              void* d_out, int out_size) {
    const float* x  = (const float*)d_in[0];
    const float* W1 = (const float*)d_in[1];
    const float* b1 = (const float*)d_in[2];
    const float* W2 = (const float*)d_in[3];
    const float* b2 = (const float*)d_in[4];
    float* out = (float*)d_out;

    static int smem_set = 0;
    if (!smem_set) {
        cudaFuncSetAttribute(k_gemm_mma, cudaFuncAttributeMaxDynamicSharedMemorySize, SMEM_DYN);
        smem_set = 1;
    }

    k_hidden<<<Mm, Dd>>>(x, W1, b1);
    k_w2conv<<<dim3(Ee / 64, Dd / 64), 256>>>(W2);
    k_gemm_mma<<<4096, 256, SMEM_DYN>>>(b2);
    k_zreduce<<<(Bsz * Ee) / 256, 256>>>();
    k_final<<<Mm / RPC, 512>>>(x, out);
}